// round 1
// baseline (speedup 1.0000x reference)
#include <cuda_runtime.h>

#define A_DIM 128
#define B_DIM 128
#define N_DIM 64
#define H_DIM 1024
#define BATCH_N 1024

// Normalized, transposed filterbanks. gamma folded into FyT.
// g_FyT[a*64 + n] = gamma * F_Y[n][a] / sum(F_Y)
// g_FxT[b*64 + m] =         F_X[m][b] / sum(F_X)
__device__ float g_FyT[A_DIM * N_DIM];
__device__ float g_FxT[B_DIM * N_DIM];

__global__ void setup_kernel(const float* __restrict__ h,
                             const float* __restrict__ Ww,
                             const float* __restrict__ Wb) {
    __shared__ float red[256];
    __shared__ float s_params[5];
    __shared__ float s_scal[5];
    int tid = threadIdx.x;

    // params[i] = dot(Ww[i,:], h[0,:]) + Wb[i]
    for (int i = 0; i < 5; i++) {
        float p = 0.f;
        for (int j = tid; j < H_DIM; j += 256) p += Ww[i * H_DIM + j] * h[j];
        red[tid] = p;
        __syncthreads();
        for (int s = 128; s > 0; s >>= 1) {
            if (tid < s) red[tid] += red[tid + s];
            __syncthreads();
        }
        if (tid == 0) s_params[i] = red[0] + Wb[i];
        __syncthreads();
    }

    if (tid == 0) {
        float gtX = s_params[0];
        float gtY = s_params[1];
        float var = expf(s_params[2] + 1e-8f);
        float dd  = expf(s_params[3]) * (float)(A_DIM - 1) / (float)(N_DIM - 1);
        float gamma = expf(s_params[4]);
        s_scal[0] = (float)(A_DIM + 1) * (gtX + 1.f) * 0.5f;  // g_X
        s_scal[1] = (float)(B_DIM + 1) * (gtY + 1.f) * 0.5f;  // g_Y
        s_scal[2] = dd;
        s_scal[3] = 1.f / (2.f * var);
        s_scal[4] = gamma;
    }
    __syncthreads();
    float gX = s_scal[0], gY = s_scal[1], dd = s_scal[2];
    float i2v = s_scal[3], gamma = s_scal[4];

    // F_X[n][a] = exp(-(a - muX[n])^2 / (2 var)); store transposed, track global sums
    float sx = 0.f, sy = 0.f;
    for (int idx = tid; idx < N_DIM * A_DIM; idx += 256) {
        int n = idx >> 7;      // 0..63
        int a = idx & 127;     // 0..127
        float off = ((float)n - (float)N_DIM * 0.5f - 0.5f) * dd;
        float muX = gX + off;
        float muY = gY + off;
        float da = (float)a - muX;
        float db = (float)a - muY;
        float fx = expf(-da * da * i2v);
        float fy = expf(-db * db * i2v);
        g_FxT[a * N_DIM + n] = fx;
        g_FyT[a * N_DIM + n] = fy;
        sx += fx;
        sy += fy;
    }
    red[tid] = sx;
    __syncthreads();
    for (int s = 128; s > 0; s >>= 1) {
        if (tid < s) red[tid] += red[tid + s];
        __syncthreads();
    }
    float sumX = red[0];
    __syncthreads();
    red[tid] = sy;
    __syncthreads();
    for (int s = 128; s > 0; s >>= 1) {
        if (tid < s) red[tid] += red[tid + s];
        __syncthreads();
    }
    float sumY = red[0];
    __syncthreads();

    float invX = 1.f / sumX;
    float invYg = gamma / sumY;
    for (int idx = tid; idx < N_DIM * A_DIM; idx += 256) {
        g_FxT[idx] *= invX;
        g_FyT[idx] *= invYg;
    }
}

// tT row stride (floats), padded to avoid bank conflicts while keeping 16B alignment
#define TSTR 68

// smem layout (floats):
//   zs  [0, 16384)          128x128
//   fyT [16384, 24576)      128x64   ([a][n])
//   fxT [24576, 32768)      128x64   ([b][m])
//   tT  [32768, 32768+128*TSTR)      ([b][n], stride TSTR)
#define SMEM_FLOATS (32768 + 128 * TSTR)

__global__ __launch_bounds__(128, 1)
void filt_kernel(const float* __restrict__ x,
                 const float* __restrict__ xh,
                 float* __restrict__ out) {
    extern __shared__ float sm[];
    float* zs  = sm;
    float* fyT = sm + 16384;
    float* fxT = sm + 24576;
    float* tT  = sm + 32768;

    int k = blockIdx.x;
    int which = blockIdx.y;
    const float* src = (which == 0 ? x : xh) + (size_t)k * (A_DIM * B_DIM);
    int tid = threadIdx.x;

    // Load z (128x128 fp32 = 64KB), coalesced float4
    {
        const float4* s4 = (const float4*)src;
        float4* z4 = (float4*)zs;
#pragma unroll
        for (int i = 0; i < 32; i++) z4[tid + i * 128] = s4[tid + i * 128];
    }
    // Load filterbanks (L2-resident after first wave)
    {
        const float4* fy4 = (const float4*)g_FyT;
        const float4* fx4 = (const float4*)g_FxT;
        float4* dfy = (float4*)fyT;
        float4* dfx = (float4*)fxT;
#pragma unroll
        for (int i = 0; i < 16; i++) {
            dfy[tid + i * 128] = fy4[tid + i * 128];
            dfx[tid + i * 128] = fx4[tid + i * 128];
        }
    }
    __syncthreads();

    // ---- Stage 1: t[n][b] = sum_a FyT[a][n] * z[a][b] ----
    // thread tile: 8n x 8b. tn = tid&7 (8 tiles), tb = tid>>3 (16 tiles).
    {
        int tn = tid & 7;
        int tb = tid >> 3;
        int n0 = tn * 8;
        int b0 = tb * 8;
        float acc[8][8];
#pragma unroll
        for (int j = 0; j < 8; j++)
#pragma unroll
            for (int i = 0; i < 8; i++) acc[j][i] = 0.f;

#pragma unroll 2
        for (int a = 0; a < A_DIM; a++) {
            float4 fA = *(const float4*)&fyT[a * 64 + n0];
            float4 fB = *(const float4*)&fyT[a * 64 + n0 + 4];
            float4 zA = *(const float4*)&zs[a * 128 + b0];
            float4 zB = *(const float4*)&zs[a * 128 + b0 + 4];
            float fv[8] = {fA.x, fA.y, fA.z, fA.w, fB.x, fB.y, fB.z, fB.w};
            float zv[8] = {zA.x, zA.y, zA.z, zA.w, zB.x, zB.y, zB.z, zB.w};
#pragma unroll
            for (int j = 0; j < 8; j++)
#pragma unroll
                for (int i = 0; i < 8; i++) acc[j][i] += fv[j] * zv[i];
        }

        // store transposed: tT[b][n]
#pragma unroll
        for (int i = 0; i < 8; i++) {
            int row = b0 + i;
            *(float4*)&tT[row * TSTR + n0] =
                make_float4(acc[0][i], acc[1][i], acc[2][i], acc[3][i]);
            *(float4*)&tT[row * TSTR + n0 + 4] =
                make_float4(acc[4][i], acc[5][i], acc[6][i], acc[7][i]);
        }
    }
    __syncthreads();

    // ---- Stage 2: out[n][m] = sum_b tT[b][n] * FxT[b][m] ----
    // thread tile: 8n x 4m. tn = tid>>4 (8 tiles), tm = tid&15 (16 tiles).
    {
        int tn = tid >> 4;
        int tm = tid & 15;
        int n0 = tn * 8;
        int m0 = tm * 4;
        float acc[8][4];
#pragma unroll
        for (int j = 0; j < 8; j++)
#pragma unroll
            for (int i = 0; i < 4; i++) acc[j][i] = 0.f;

#pragma unroll 2
        for (int b = 0; b < B_DIM; b++) {
            float4 tA = *(const float4*)&tT[b * TSTR + n0];
            float4 tB = *(const float4*)&tT[b * TSTR + n0 + 4];
            float4 fx = *(const float4*)&fxT[b * 64 + m0];
            float tv[8] = {tA.x, tA.y, tA.z, tA.w, tB.x, tB.y, tB.z, tB.w};
            float xv[4] = {fx.x, fx.y, fx.z, fx.w};
#pragma unroll
            for (int j = 0; j < 8; j++)
#pragma unroll
                for (int i = 0; i < 4; i++) acc[j][i] += tv[j] * xv[i];
        }

        float* obase = out + (size_t)k * (2 * N_DIM * N_DIM) + which * (N_DIM * N_DIM);
#pragma unroll
        for (int j = 0; j < 8; j++) {
            *(float4*)&obase[(n0 + j) * N_DIM + m0] =
                make_float4(acc[j][0], acc[j][1], acc[j][2], acc[j][3]);
        }
    }
}

extern "C" void kernel_launch(void* const* d_in, const int* in_sizes, int n_in,
                              void* d_out, int out_size) {
    const float* x  = (const float*)d_in[0];
    const float* xh = (const float*)d_in[1];
    const float* h  = (const float*)d_in[2];
    const float* Ww = (const float*)d_in[3];
    const float* Wb = (const float*)d_in[4];
    float* out = (float*)d_out;

    cudaFuncSetAttribute(filt_kernel, cudaFuncAttributeMaxDynamicSharedMemorySize,
                         SMEM_FLOATS * sizeof(float));

    setup_kernel<<<1, 256>>>(h, Ww, Wb);

    dim3 grid(BATCH_N, 2);
    filt_kernel<<<grid, 128, SMEM_FLOATS * sizeof(float)>>>(x, xh, out);
}

// round 2
// speedup vs baseline: 1.2477x; 1.2477x over previous
#include <cuda_runtime.h>

#define A_DIM 128
#define B_DIM 128
#define N_DIM 64
#define H_DIM 1024
#define BATCH_N 1024

typedef unsigned long long u64;

// packed f32x2 helpers (Blackwell FFMA2 path — only reachable via PTX)
__device__ __forceinline__ u64 pack2(float lo, float hi) {
    u64 r;
    asm("mov.b64 %0, {%1, %2};" : "=l"(r) : "f"(lo), "f"(hi));
    return r;
}
__device__ __forceinline__ void fma2(u64& d, u64 a, u64 b) {
    asm("fma.rn.f32x2 %0, %1, %2, %0;" : "+l"(d) : "l"(a), "l"(b));
}

// Normalized, transposed filterbanks. gamma folded into FyT.
__device__ float g_FyT[A_DIM * N_DIM];
__device__ float g_FxT[B_DIM * N_DIM];

__global__ void setup_kernel(const float* __restrict__ h,
                             const float* __restrict__ Ww,
                             const float* __restrict__ Wb) {
    __shared__ float red[256];
    __shared__ float s_params[5];
    __shared__ float s_scal[5];
    int tid = threadIdx.x;

    for (int i = 0; i < 5; i++) {
        float p = 0.f;
        for (int j = tid; j < H_DIM; j += 256) p += Ww[i * H_DIM + j] * h[j];
        red[tid] = p;
        __syncthreads();
        for (int s = 128; s > 0; s >>= 1) {
            if (tid < s) red[tid] += red[tid + s];
            __syncthreads();
        }
        if (tid == 0) s_params[i] = red[0] + Wb[i];
        __syncthreads();
    }

    if (tid == 0) {
        float gtX = s_params[0];
        float gtY = s_params[1];
        float var = expf(s_params[2] + 1e-8f);
        float dd  = expf(s_params[3]) * (float)(A_DIM - 1) / (float)(N_DIM - 1);
        float gamma = expf(s_params[4]);
        s_scal[0] = (float)(A_DIM + 1) * (gtX + 1.f) * 0.5f;
        s_scal[1] = (float)(B_DIM + 1) * (gtY + 1.f) * 0.5f;
        s_scal[2] = dd;
        s_scal[3] = 1.f / (2.f * var);
        s_scal[4] = gamma;
    }
    __syncthreads();
    float gX = s_scal[0], gY = s_scal[1], dd = s_scal[2];
    float i2v = s_scal[3], gamma = s_scal[4];

    float sx = 0.f, sy = 0.f;
    for (int idx = tid; idx < N_DIM * A_DIM; idx += 256) {
        int n = idx >> 7;
        int a = idx & 127;
        float off = ((float)n - (float)N_DIM * 0.5f - 0.5f) * dd;
        float muX = gX + off;
        float muY = gY + off;
        float da = (float)a - muX;
        float db = (float)a - muY;
        float fx = expf(-da * da * i2v);
        float fy = expf(-db * db * i2v);
        g_FxT[a * N_DIM + n] = fx;
        g_FyT[a * N_DIM + n] = fy;
        sx += fx;
        sy += fy;
    }
    red[tid] = sx;
    __syncthreads();
    for (int s = 128; s > 0; s >>= 1) {
        if (tid < s) red[tid] += red[tid + s];
        __syncthreads();
    }
    float sumX = red[0];
    __syncthreads();
    red[tid] = sy;
    __syncthreads();
    for (int s = 128; s > 0; s >>= 1) {
        if (tid < s) red[tid] += red[tid + s];
        __syncthreads();
    }
    float sumY = red[0];
    __syncthreads();

    float invX = 1.f / sumX;
    float invYg = gamma / sumY;
    for (int idx = tid; idx < N_DIM * A_DIM; idx += 256) {
        g_FxT[idx] *= invX;
        g_FyT[idx] *= invYg;
    }
}

#define TSTR 68
// smem floats: zs 16384 | fyT 8192 | fxT 8192 | tT 128*TSTR
#define SMEM_FLOATS (32768 + 128 * TSTR)

__global__ __launch_bounds__(256, 1)
void filt_kernel(const float* __restrict__ x,
                 const float* __restrict__ xh,
                 float* __restrict__ out) {
    extern __shared__ float sm[];
    float* zs  = sm;
    float* fyT = sm + 16384;
    float* fxT = sm + 24576;
    float* tT  = sm + 32768;

    int k = blockIdx.x;
    int which = blockIdx.y;
    const float* src = (which == 0 ? x : xh) + (size_t)k * (A_DIM * B_DIM);
    int tid = threadIdx.x;

    // stage z (64KB) + filterbanks (2x32KB), coalesced float4
    {
        const float4* s4 = (const float4*)src;
        float4* z4 = (float4*)zs;
#pragma unroll
        for (int i = 0; i < 16; i++) z4[tid + i * 256] = s4[tid + i * 256];

        const float4* fy4 = (const float4*)g_FyT;
        const float4* fx4 = (const float4*)g_FxT;
        float4* dfy = (float4*)fyT;
        float4* dfx = (float4*)fxT;
#pragma unroll
        for (int i = 0; i < 8; i++) {
            dfy[tid + i * 256] = fy4[tid + i * 256];
            dfx[tid + i * 256] = fx4[tid + i * 256];
        }
    }
    __syncthreads();

    // ---- Stage 1: t[n][b] = sum_a FyT[a][n] * z[a][b]  (packed over n) ----
    // thread tile 8n x 4b; tid bits: [1:0]=b-sub, [4:2]=n-tile, [7:5]=b-group
    {
        int b0 = (tid & 3) * 4 + (tid >> 5) * 16;
        int n0 = ((tid >> 2) & 7) * 8;

        u64 acc[4][4];  // [n-pair][b]
#pragma unroll
        for (int j = 0; j < 4; j++)
#pragma unroll
            for (int i = 0; i < 4; i++) acc[j][i] = 0ull;

#pragma unroll 4
        for (int a = 0; a < A_DIM; a++) {
            ulonglong2 f01 = *(const ulonglong2*)&fyT[a * 64 + n0];
            ulonglong2 f23 = *(const ulonglong2*)&fyT[a * 64 + n0 + 4];
            float4 zv = *(const float4*)&zs[a * 128 + b0];
            u64 fp[4] = {f01.x, f01.y, f23.x, f23.y};
            u64 zb[4] = {pack2(zv.x, zv.x), pack2(zv.y, zv.y),
                         pack2(zv.z, zv.z), pack2(zv.w, zv.w)};
#pragma unroll
            for (int j = 0; j < 4; j++)
#pragma unroll
                for (int i = 0; i < 4; i++) fma2(acc[j][i], fp[j], zb[i]);
        }

        // store transposed: tT[b][n0..n0+7]
#pragma unroll
        for (int i = 0; i < 4; i++) {
            int row = b0 + i;
            ulonglong2 s0, s1;
            s0.x = acc[0][i]; s0.y = acc[1][i];
            s1.x = acc[2][i]; s1.y = acc[3][i];
            *(ulonglong2*)&tT[row * TSTR + n0] = s0;
            *(ulonglong2*)&tT[row * TSTR + n0 + 4] = s1;
        }
    }
    __syncthreads();

    // ---- Stage 2: out[n][m] = sum_b tT[b][n] * FxT[b][m]  (packed over m) ----
    // thread tile 4n x 4m; tid bits: [3:0]=m-tile, [7:4]=n-tile
    {
        int m0 = (tid & 15) * 4;
        int n0 = (tid >> 4) * 4;

        u64 acc[4][2];  // [n][m-pair]
#pragma unroll
        for (int j = 0; j < 4; j++) {
            acc[j][0] = 0ull;
            acc[j][1] = 0ull;
        }

#pragma unroll 4
        for (int b = 0; b < B_DIM; b++) {
            float4 tv = *(const float4*)&tT[b * TSTR + n0];
            ulonglong2 fxp = *(const ulonglong2*)&fxT[b * 64 + m0];
            u64 tp[4] = {pack2(tv.x, tv.x), pack2(tv.y, tv.y),
                         pack2(tv.z, tv.z), pack2(tv.w, tv.w)};
#pragma unroll
            for (int j = 0; j < 4; j++) {
                fma2(acc[j][0], tp[j], fxp.x);
                fma2(acc[j][1], tp[j], fxp.y);
            }
        }

        float* obase = out + (size_t)k * (2 * N_DIM * N_DIM) + which * (N_DIM * N_DIM);
#pragma unroll
        for (int j = 0; j < 4; j++) {
            ulonglong2 s;
            s.x = acc[j][0];
            s.y = acc[j][1];
            *(ulonglong2*)&obase[(n0 + j) * N_DIM + m0] = s;
        }
    }
}

extern "C" void kernel_launch(void* const* d_in, const int* in_sizes, int n_in,
                              void* d_out, int out_size) {
    const float* x  = (const float*)d_in[0];
    const float* xh = (const float*)d_in[1];
    const float* h  = (const float*)d_in[2];
    const float* Ww = (const float*)d_in[3];
    const float* Wb = (const float*)d_in[4];
    float* out = (float*)d_out;

    cudaFuncSetAttribute(filt_kernel, cudaFuncAttributeMaxDynamicSharedMemorySize,
                         SMEM_FLOATS * sizeof(float));

    setup_kernel<<<1, 256>>>(h, Ww, Wb);

    dim3 grid(BATCH_N, 2);
    filt_kernel<<<grid, 256, SMEM_FLOATS * sizeof(float)>>>(x, xh, out);
}